// round 8
// baseline (speedup 1.0000x reference)
#include <cuda_runtime.h>
#include <cstdint>

__device__ double   g_acc[2];   // [0]=flow0 (kz=3), [1]=flow1 (kz=5)
__device__ unsigned g_cnt = 0;

#define CP_ASYNC16(dst, src) \
    asm volatile("cp.async.cg.shared.global [%0], [%1], 16;\n" :: "r"(dst), "l"(src))
#define CP_COMMIT() asm volatile("cp.async.commit_group;\n" ::: "memory")
#define CP_WAIT(n)  asm volatile("cp.async.wait_group %0;\n" :: "n"(n) : "memory")

// ---------------- heavy path: kz=5, W=256, cp.async ring ----------------
// Ring: 8 slots x 256 floats (warp-private). Prefetch 8 rows up front; each
// iteration waits with 2 groups outstanding (rows <= ii+5 guaranteed), reads
// gd=row ii / gn=row ii+5 from smem, slides V0/Va, then prefetches row ii+8
// into the freed slot. Analytic-S2 accounting identical to R7.
__device__ __forceinline__ void heavy_strip(const float* __restrict__ plane,
                                            float* __restrict__ ring_f,
                                            uint32_t ring_u,
                                            int i0, int rows, int own_hi,
                                            int lane,
                                            float& pA, float& pB, float& wg2) {
    constexpr int   KZ = 5, W = 256, CPT = 8, NC = 12, HOUT = 252;
    constexpr float m  = 2.0f;

    const int col0   = min(lane * CPT, W - NC);
    const int own_lo = lane * CPT;
    const int own_hc = min(own_lo + CPT, HOUT);

    float ccq[NC];
#pragma unroll
    for (int q = 0; q < NC; ++q) {
        const int jg = col0 + q;
        const bool own = (jg >= own_lo) && (jg < own_lo + CPT);
        const int v = min(jg, KZ - 1) - max(0, jg - (HOUT - 1)) + 1;
        ccq[q] = own ? (float)max(v, 0) : 0.f;
    }

    // ---- prefetch 8 rows (one commit group per row) ----
#pragma unroll
    for (int s = 0; s < 8; ++s) {
        const int r = min(i0 + s, W - 1);
        const float* src = plane + (size_t)r * W + lane * 8;
        const uint32_t dst = ring_u + (uint32_t)s * 1024u + (uint32_t)lane * 32u;
        CP_ASYNC16(dst, src);
        CP_ASYNC16(dst + 16u, src + 4);
        CP_COMMIT();
    }
    CP_WAIT(2);            // rows 0..5 resident
    __syncwarp();

    // ---- init V over rows 0..4 from smem ----
    float V0[NC], Va[NC];
#pragma unroll
    for (int c = 0; c < NC; ++c) { V0[c] = 0.f; Va[c] = 0.f; }
#pragma unroll
    for (int a = 0; a < KZ; ++a) {
        const float* rp = ring_f + a * 256 + col0;
        float g[NC];
#pragma unroll
        for (int v = 0; v < 3; ++v) {
            float4 t = *reinterpret_cast<const float4*>(rp + v * 4);
            g[v*4+0]=t.x; g[v*4+1]=t.y; g[v*4+2]=t.z; g[v*4+3]=t.w;
        }
        const int rg = i0 + a;
        const float crf = (rg < own_hi)
            ? (float)max(min(rg, KZ - 1) - max(0, rg - (HOUT - 1)) + 1, 0) : 0.f;
        float rowacc = 0.f;
#pragma unroll
        for (int q = 0; q < NC; ++q) {
            V0[q] += g[q];
            Va[q] = fmaf((float)a - m, g[q], Va[q]);
            rowacc = fmaf(ccq[q], g[q] * g[q], rowacc);
        }
        wg2 = fmaf(crf, rowacc, wg2);
    }

    // ---- main loop ----
    for (int ii = 0; ii < rows; ++ii) {
        // Horizontal sliding windows from V (registers only).
        float S0 = 0.f, Sa = 0.f, Sc = 0.f;
#pragma unroll
        for (int c = 0; c < KZ; ++c) {
            S0 += V0[c];
            Sc = fmaf((float)c - m, V0[c], Sc);
            Sa += Va[c];
        }
#pragma unroll
        for (int j = 0; j < CPT; ++j) {
            const int jg = col0 + j;
            if (jg >= own_lo && jg < own_hc) {
                pA = fmaf(Sa, Sa, pA);
                pA = fmaf(Sc, Sc, pA);
                pB = fmaf(S0, S0, pB);
            }
            if (j + 1 < CPT) {
                const float d0 = V0[j], dn = V0[j + KZ];
                Sc = Sc - S0;
                Sc = fmaf(m + 1.f, d0, Sc);
                Sc = fmaf(m, dn, Sc);
                S0 += dn - d0;
                Sa += Va[j + KZ] - Va[j];
            }
        }

        if (ii + 1 < rows) {
            CP_WAIT(2);                 // rows <= ii+5 resident
            __syncwarp();
            const float* pgd = ring_f + (size_t)(ii & 7) * 256 + col0;
            const float* pgn = ring_f + (size_t)((ii + 5) & 7) * 256 + col0;
            float gd[NC], gn[NC];
#pragma unroll
            for (int v = 0; v < 3; ++v) {
                float4 td = *reinterpret_cast<const float4*>(pgd + v * 4);
                float4 tn = *reinterpret_cast<const float4*>(pgn + v * 4);
                gd[v*4+0]=td.x; gd[v*4+1]=td.y; gd[v*4+2]=td.z; gd[v*4+3]=td.w;
                gn[v*4+0]=tn.x; gn[v*4+1]=tn.y; gn[v*4+2]=tn.z; gn[v*4+3]=tn.w;
            }
            const int rg = i0 + ii + KZ;
            const float crf = (rg < own_hi)
                ? (float)max(min(rg, KZ - 1) - max(0, rg - (HOUT - 1)) + 1, 0) : 0.f;
            float rowacc = 0.f;
#pragma unroll
            for (int q = 0; q < NC; ++q) {
                float t = Va[q] - V0[q];
                t = fmaf(m + 1.f, gd[q], t);
                Va[q] = fmaf(m, gn[q], t);
                V0[q] += gn[q] - gd[q];
                rowacc = fmaf(ccq[q], gn[q] * gn[q], rowacc);
            }
            wg2 = fmaf(crf, rowacc, wg2);

            // Prefetch row ii+8 into the slot just freed by row ii.
            const int r = min(i0 + ii + 8, W - 1);
            const float* src = plane + (size_t)r * W + lane * 8;
            const uint32_t dst = ring_u + (uint32_t)((ii + 8) & 7) * 1024u
                                        + (uint32_t)lane * 32u;
            CP_ASYNC16(dst, src);
            CP_ASYNC16(dst + 16u, src + 4);
            CP_COMMIT();
        }
    }
    CP_WAIT(0);            // drain before the ring is reused for reduction
    __syncwarp();
}

// ---------------- light path: kz=3, W=128 (R7 code, global loads) --------
__device__ __forceinline__ void light_strip(const float* __restrict__ plane,
                                            int i0, int rows, int own_hi,
                                            int lane,
                                            float& pA, float& pB, float& wg2) {
    constexpr int   KZ = 3, W = 128, CPT = 4, NLD = 2, NC = 8, HOUT = 126;
    constexpr int   JMAX = NC - KZ + 1;
    constexpr float m = 1.0f;

    const int col0   = min(lane * CPT, W - NC);
    const int own_lo = lane * CPT;
    const int own_hc = min(own_lo + CPT, HOUT);

    float ccq[NC];
#pragma unroll
    for (int q = 0; q < NC; ++q) {
        const int jg = col0 + q;
        const bool own = (jg >= own_lo) && (jg < own_lo + CPT);
        const int v = min(jg, KZ - 1) - max(0, jg - (HOUT - 1)) + 1;
        ccq[q] = own ? (float)max(v, 0) : 0.f;
    }

    const float* __restrict__ p = plane + (size_t)i0 * W + col0;

    float V0[NC], Va[NC];
#pragma unroll
    for (int c = 0; c < NC; ++c) { V0[c] = 0.f; Va[c] = 0.f; }

#pragma unroll
    for (int a = 0; a < KZ; ++a) {
        float g[NC];
#pragma unroll
        for (int v = 0; v < NLD; ++v) {
            float4 t = *reinterpret_cast<const float4*>(p + (size_t)a * W + v * 4);
            g[v*4+0]=t.x; g[v*4+1]=t.y; g[v*4+2]=t.z; g[v*4+3]=t.w;
        }
        const int rg = i0 + a;
        const float crf = (rg < own_hi)
            ? (float)max(min(rg, KZ - 1) - max(0, rg - (HOUT - 1)) + 1, 0) : 0.f;
        float rowacc = 0.f;
#pragma unroll
        for (int q = 0; q < NC; ++q) {
            V0[q] += g[q];
            Va[q] = fmaf((float)a - m, g[q], Va[q]);
            rowacc = fmaf(ccq[q], g[q] * g[q], rowacc);
        }
        wg2 = fmaf(crf, rowacc, wg2);
    }

    for (int ii = 0; ii < rows; ++ii) {
        const bool doSlide = (ii + 1 < rows);
        float gn[NC], gd[NC];
        if (doSlide) {
            const float* pn = p + (size_t)(ii + KZ) * W;
            const float* po = p + (size_t)ii * W;
#pragma unroll
            for (int v = 0; v < NLD; ++v) {
                float4 tn = *reinterpret_cast<const float4*>(pn + v * 4);
                float4 to = *reinterpret_cast<const float4*>(po + v * 4);
                gn[v*4+0]=tn.x; gn[v*4+1]=tn.y; gn[v*4+2]=tn.z; gn[v*4+3]=tn.w;
                gd[v*4+0]=to.x; gd[v*4+1]=to.y; gd[v*4+2]=to.z; gd[v*4+3]=to.w;
            }
        }

        float S0 = 0.f, Sa = 0.f, Sc = 0.f;
#pragma unroll
        for (int c = 0; c < KZ; ++c) {
            S0 += V0[c];
            Sc = fmaf((float)c - m, V0[c], Sc);
            Sa += Va[c];
        }
#pragma unroll
        for (int j = 0; j < JMAX; ++j) {
            const int jg = col0 + j;
            if (jg >= own_lo && jg < own_hc) {
                pA = fmaf(Sa, Sa, pA);
                pA = fmaf(Sc, Sc, pA);
                pB = fmaf(S0, S0, pB);
            }
            if (j + 1 < JMAX) {
                const float d0 = V0[j], dn = V0[j + KZ];
                Sc = Sc - S0;
                Sc = fmaf(m + 1.f, d0, Sc);
                Sc = fmaf(m, dn, Sc);
                S0 += dn - d0;
                Sa += Va[j + KZ] - Va[j];
            }
        }

        if (doSlide) {
            const int rg = i0 + ii + KZ;
            const float crf = (rg < own_hi)
                ? (float)max(min(rg, KZ - 1) - max(0, rg - (HOUT - 1)) + 1, 0) : 0.f;
            float rowacc = 0.f;
#pragma unroll
            for (int q = 0; q < NC; ++q) {
                float t = Va[q] - V0[q];
                t = fmaf(m + 1.f, gd[q], t);
                Va[q] = fmaf(m, gn[q], t);
                V0[q] += gn[q] - gd[q];
                rowacc = fmaf(ccq[q], gn[q] * gn[q], rowacc);
            }
            wg2 = fmaf(crf, rowacc, wg2);
        }
    }
}

// 296 blocks x 8 warps; exactly 2 blocks per SM. Warps 0..5 heavy, 6..7 light.
//   heavy: 1776 tasks (48 planes x 28 chunks of 9; 16 planes x 27 chunks 10/9).
//   light:  592 tasks (48 planes x 9 chunks of 14; 16 planes x 10 chunks 13/12).
__global__ __launch_bounds__(256, 2)
void fused_loss_kernel(const float* __restrict__ f0,
                       const float* __restrict__ f1,
                       float* __restrict__ out) {
    __shared__ __align__(16) float s_ring[6 * 8 * 256];   // 48 KB: 6 heavy rings

    const int wid  = threadIdx.x >> 5;
    const int lane = threadIdx.x & 31;

    float pA = 0.f, pB = 0.f, wg2 = 0.f;
    float partial;

    if (wid < 6) {                                // heavy: kz=5 on flow1
        const int h = blockIdx.x * 6 + wid;       // 0..1775
        int plane, i0, rows; bool last;
        if (h < 1344) {
            plane = h / 28; const int c = h % 28;
            i0 = c * 9; rows = 9; last = (c == 27);
        } else {
            const int k = h - 1344;
            plane = 48 + k / 27; const int c = k % 27;
            if (c < 9) { i0 = c * 10; rows = 10; }
            else       { i0 = 90 + (c - 9) * 9; rows = 9; }
            last = (c == 26);
        }
        const int own_hi = last ? 256 : (i0 + rows);
        float*   ring_f = s_ring + wid * 2048;
        uint32_t ring_u = (uint32_t)__cvta_generic_to_shared(s_ring)
                        + (uint32_t)wid * 8192u;
        heavy_strip(f1 + (size_t)plane * 256 * 256, ring_f, ring_u,
                    i0, rows, own_hi, lane, pA, pB, wg2);
        constexpr float invD1 = 12.0f / (25.0f * 24.0f);
        constexpr float invD0 = 1.0f / 25.0f;
        partial = wg2 - pA * invD1 - pB * invD0;
    } else {                                      // light: kz=3 on flow0
        const int l = blockIdx.x * 2 + (wid - 6); // 0..591
        int plane, i0, rows; bool last;
        if (l < 432) {
            plane = l / 9; const int c = l % 9;
            i0 = c * 14; rows = 14; last = (c == 8);
        } else {
            const int k = l - 432;
            plane = 48 + k / 10; const int c = k % 10;
            if (c < 6) { i0 = c * 13; rows = 13; }
            else       { i0 = 78 + (c - 6) * 12; rows = 12; }
            last = (c == 9);
        }
        const int own_hi = last ? 128 : (i0 + rows);
        light_strip(f0 + (size_t)plane * 128 * 128,
                    i0, rows, own_hi, lane, pA, pB, wg2);
        constexpr float invD1 = 12.0f / (9.0f * 8.0f);
        constexpr float invD0 = 1.0f / 9.0f;
        partial = wg2 - pA * invD1 - pB * invD0;
    }

#pragma unroll
    for (int off = 16; off > 0; off >>= 1)
        partial += __shfl_down_sync(0xffffffffu, partial, off);

    // Reuse ring smem for the block reduction (heavy rings drained above).
    __syncthreads();
    double* shd = reinterpret_cast<double*>(s_ring);
    if (lane == 0) shd[wid] = (double)partial;
    __syncthreads();

    if (threadIdx.x == 0) {
        double a1 = shd[0] + shd[1] + shd[2] + shd[3] + shd[4] + shd[5];
        double a0 = shd[6] + shd[7];
        atomicAdd(&g_acc[0], a0);
        atomicAdd(&g_acc[1], a1);
        __threadfence();
        const unsigned done = atomicAdd(&g_cnt, 1);
        if (done == gridDim.x - 1) {              // last block: finalize + reset
            __threadfence();
            const double r0 = g_acc[0], r1 = g_acc[1];
            out[0] = (float)(r0 / (32.0 * 126.0 * 126.0) +
                             r1 / (32.0 * 252.0 * 252.0));
            g_acc[0] = 0.0; g_acc[1] = 0.0; g_cnt = 0u;
        }
    }
}

extern "C" void kernel_launch(void* const* d_in, const int* in_sizes, int n_in,
                              void* d_out, int out_size) {
    const float* flow0 = (const float*)d_in[0];  // (32, 2, 128, 128)
    const float* flow1 = (const float*)d_in[1];  // (32, 2, 256, 256)
    if (n_in >= 2 && in_sizes[0] > in_sizes[1]) {
        const float* t = flow0; flow0 = flow1; flow1 = t;
    }
    fused_loss_kernel<<<296, 256>>>(flow0, flow1, (float*)d_out);
}